// round 3
// baseline (speedup 1.0000x reference)
#include <cuda_runtime.h>
#include <cuda_bf16.h>
#include <cstdint>

// NeRF volume rendering compositing, GB300.
// rgb: [B, 64, 3] f32, sigma: [B, 64] f32
// out: [B*3] rgb_map ++ [B] depth_map (f32)
//
// 8 lanes per ray (8 samples/lane), 4 rays/warp, 32 rays/block.
// Block stages inputs to smem via coalesced float4 (8 LDG.128/thread, MLP 8),
// then per-segment Kogge-Stone product scan (3 shfl) + segment butterfly
// reduction (12 shfl) -> 4 shuffles per ray vs 26 in the warp-per-ray version.

#define NERF_S 64
#define RAYS_PER_BLOCK 32
#define THREADS 256

__global__ __launch_bounds__(THREADS) void nerf_render_kernel(
    const float4* __restrict__ rgb4,   // [B*48] float4
    const float4* __restrict__ sig4,   // [B*16] float4
    float* __restrict__ out,
    int n_rays)
{
    __shared__ float4 s_rgb[RAYS_PER_BLOCK * 48];  // 24 KB
    __shared__ float4 s_sig[RAYS_PER_BLOCK * 16];  // 8 KB

    const int t = threadIdx.x;
    const int ray0 = blockIdx.x * RAYS_PER_BLOCK;

    // ---- stage (all loads front-batched, fully coalesced 16B) ----
    const float4* grgb = rgb4 + (size_t)ray0 * 48;
    const float4* gsig = sig4 + (size_t)ray0 * 16;
    float4 r0 = grgb[t];
    float4 r1 = grgb[t + 256];
    float4 r2 = grgb[t + 512];
    float4 r3 = grgb[t + 768];
    float4 r4 = grgb[t + 1024];
    float4 r5 = grgb[t + 1280];
    float4 s0 = gsig[t];
    float4 s1 = gsig[t + 256];
    s_rgb[t]        = r0;
    s_rgb[t + 256]  = r1;
    s_rgb[t + 512]  = r2;
    s_rgb[t + 768]  = r3;
    s_rgb[t + 1024] = r4;
    s_rgb[t + 1280] = r5;
    s_sig[t]        = s0;
    s_sig[t + 256]  = s1;
    __syncthreads();

    // ---- compute: lane mapping ----
    const int lane = t & 31;
    const int wid  = t >> 5;
    const int rsub = lane >> 3;            // ray within warp (0..3)
    const int j    = lane & 7;             // segment position (0..7)
    const int ray_l = wid * 4 + rsub;      // ray within block
    const int ray   = ray0 + ray_l;

    // sigma: samples 8j..8j+7
    float4 sa = s_sig[ray_l * 16 + 2 * j];
    float4 sb = s_sig[ray_l * 16 + 2 * j + 1];
    // rgb: 24 floats = 6 float4
    float4 c[6];
    #pragma unroll
    for (int i = 0; i < 6; i++) c[i] = s_rgb[ray_l * 48 + 6 * j + i];

    float e[8];
    e[0] = __expf(-sa.x); e[1] = __expf(-sa.y);
    e[2] = __expf(-sa.z); e[3] = __expf(-sa.w);
    e[4] = __expf(-sb.x); e[5] = __expf(-sb.y);
    e[6] = __expf(-sb.z); e[7] = __expf(-sb.w);

    // local exclusive products of t_i = e_i + 1e-10
    float lex[8];
    float run = 1.0f;
    #pragma unroll
    for (int i = 0; i < 8; i++) { lex[i] = run; run *= e[i] + 1e-10f; }

    // segment-inclusive product scan over 8 lanes (3 steps)
    float seg = run;
    #pragma unroll
    for (int off = 1; off < 8; off <<= 1) {
        float v = __shfl_up_sync(0xffffffffu, seg, off);
        if (j >= off) seg *= v;
    }
    // exclusive
    float E = __shfl_up_sync(0xffffffffu, seg, 1);
    if (j == 0) E = 1.0f;

    // weights + weighted sums
    const float* cf = (const float*)c;
    const float step = 4.0f / 63.0f;        // linspace(2, 6, 64)
    const float tv0 = 2.0f + step * (float)(8 * j);
    float racc = 0.f, gacc = 0.f, bacc = 0.f, dacc = 0.f;
    #pragma unroll
    for (int i = 0; i < 8; i++) {
        float w = (1.0f - e[i]) * (E * lex[i]);
        racc += w * cf[3 * i + 0];
        gacc += w * cf[3 * i + 1];
        bacc += w * cf[3 * i + 2];
        dacc += w * (tv0 + step * (float)i);
    }

    // segment butterfly reduction (stays within 8-lane segment)
    #pragma unroll
    for (int off = 4; off > 0; off >>= 1) {
        racc += __shfl_xor_sync(0xffffffffu, racc, off);
        gacc += __shfl_xor_sync(0xffffffffu, gacc, off);
        bacc += __shfl_xor_sync(0xffffffffu, bacc, off);
        dacc += __shfl_xor_sync(0xffffffffu, dacc, off);
    }

    if (j == 0 && ray < n_rays) {
        out[(size_t)ray * 3 + 0] = racc;
        out[(size_t)ray * 3 + 1] = gacc;
        out[(size_t)ray * 3 + 2] = bacc;
        out[(size_t)n_rays * 3 + ray] = dacc;
    }
}

extern "C" void kernel_launch(void* const* d_in, const int* in_sizes, int n_in,
                              void* d_out, int out_size)
{
    const float4* rgb4 = (const float4*)d_in[0];   // [B, 64, 3]
    const float4* sig4 = (const float4*)d_in[1];   // [B, 64]
    float* out = (float*)d_out;

    const int n_rays = in_sizes[1] / NERF_S;
    const int blocks = (n_rays + RAYS_PER_BLOCK - 1) / RAYS_PER_BLOCK;
    nerf_render_kernel<<<blocks, THREADS>>>(rgb4, sig4, out, n_rays);
}

// round 4
// speedup vs baseline: 1.3367x; 1.3367x over previous
#include <cuda_runtime.h>
#include <cuda_bf16.h>
#include <cstdint>

// NeRF volume rendering compositing, GB300 (sm_103a).
// rgb: [B, 64, 3] f32, sigma: [B, 64] f32
// out: [B*3] rgb_map ++ [B] depth_map (f32)
//
// 2 rays per warp, 16 lanes per ray, 4 samples per lane.
// No smem, no block barriers: warps fully autonomous so load/compute phases
// of different warps overlap freely. 4 front-batched LDG.128 per warp
// (1 sigma + 3 rgb), all streaming (__ldcs). Segmented (width=16) shuffle
// scan + reduction.

#define NERF_S 64

__global__ __launch_bounds__(256) void nerf_render_kernel(
    const float4* __restrict__ rgb4,   // [B*48] float4
    const float4* __restrict__ sig4,   // [B*16] float4
    float* __restrict__ out,
    int n_rays)
{
    const int warp_g = (blockIdx.x * blockDim.x + threadIdx.x) >> 5;
    const int lane   = threadIdx.x & 31;
    const int half   = lane >> 4;          // 0 = ray A, 1 = ray B
    const int j      = lane & 15;          // segment position (0..15)
    const int ray    = warp_g * 2 + half;
    if (ray >= n_rays) return;

    // ---- front-batched streaming loads (fully coalesced LDG.128) ----
    // sigma: warp covers 512B = both rays; lane l -> ray (l>>4), samples 4j..4j+3
    const float4 sg = __ldcs(sig4 + (size_t)warp_g * 32 + lane);

    // rgb: lane needs 12 floats at ray*192 + 12*j  (three float4, 16B aligned)
    const float4* rp = rgb4 + ((size_t)ray * 192 + 12 * j) / 4;
    float4 c0 = __ldcs(rp + 0);
    float4 c1 = __ldcs(rp + 1);
    float4 c2 = __ldcs(rp + 2);

    // ---- per-sample transmittance factors ----
    float e0 = __expf(-sg.x);
    float e1 = __expf(-sg.y);
    float e2 = __expf(-sg.z);
    float e3 = __expf(-sg.w);

    float t0 = e0 + 1e-10f;
    float t1 = e1 + 1e-10f;
    float t2 = e2 + 1e-10f;
    float t3 = e3 + 1e-10f;

    // local exclusive products
    float l1 = t0;
    float l2 = t0 * t1;
    float l3 = l2 * t2;
    float p  = l3 * t3;               // local total product

    // ---- width-16 inclusive product scan (4 steps) ----
    float incl = p;
    #pragma unroll
    for (int off = 1; off < 16; off <<= 1) {
        float v = __shfl_up_sync(0xffffffffu, incl, off, 16);
        if (j >= off) incl *= v;
    }
    float E = __shfl_up_sync(0xffffffffu, incl, 1, 16);  // exclusive
    if (j == 0) E = 1.0f;

    // weights
    float w0 = (1.0f - e0) * E;
    float w1 = (1.0f - e1) * (E * l1);
    float w2 = (1.0f - e2) * (E * l2);
    float w3 = (1.0f - e3) * (E * l3);

    // ---- weighted sums ----
    float r = w0 * c0.x + w1 * c0.w + w2 * c1.z + w3 * c2.y;
    float g = w0 * c0.y + w1 * c1.x + w2 * c1.w + w3 * c2.z;
    float b = w0 * c0.z + w1 * c1.y + w2 * c2.x + w3 * c2.w;

    const float step = 4.0f / 63.0f;      // linspace(2, 6, 64)
    const float tv = 2.0f + step * (float)(4 * j);
    float d = w0 * tv
            + w1 * (tv + step)
            + w2 * (tv + 2.0f * step)
            + w3 * (tv + 3.0f * step);

    // ---- width-16 butterfly reduction (shared by the 2 rays) ----
    #pragma unroll
    for (int off = 8; off > 0; off >>= 1) {
        r += __shfl_xor_sync(0xffffffffu, r, off, 16);
        g += __shfl_xor_sync(0xffffffffu, g, off, 16);
        b += __shfl_xor_sync(0xffffffffu, b, off, 16);
        d += __shfl_xor_sync(0xffffffffu, d, off, 16);
    }

    if (j == 0) {
        out[(size_t)ray * 3 + 0] = r;
        out[(size_t)ray * 3 + 1] = g;
        out[(size_t)ray * 3 + 2] = b;
        out[(size_t)n_rays * 3 + ray] = d;
    }
}

extern "C" void kernel_launch(void* const* d_in, const int* in_sizes, int n_in,
                              void* d_out, int out_size)
{
    const float4* rgb4 = (const float4*)d_in[0];   // [B, 64, 3]
    const float4* sig4 = (const float4*)d_in[1];   // [B, 64]
    float* out = (float*)d_out;

    const int n_rays = in_sizes[1] / NERF_S;

    // 256 threads = 8 warps = 16 rays per block
    const int rays_per_block = 16;
    const int blocks = (n_rays + rays_per_block - 1) / rays_per_block;
    nerf_render_kernel<<<blocks, 256>>>(rgb4, sig4, out, n_rays);
}